// round 6
// baseline (speedup 1.0000x reference)
#include <cuda_runtime.h>
#include <math.h>

#define NNODES 50000
#define DEGC 16
#define RECS 208   // record stride (floats): y0[64] y1[64] z[64] el[2] er[2] xg2[2] xg1[2]

// ---------------- scratch (device globals) ---------------------------------
__device__ float g_rec[NNODES * RECS];
__device__ float g_gy[NNODES * 64];     // gate-weighted attn contribution (merge space)
__device__ float g_vlr[128 * 4];        // [k][el0,el1,er0,er1]
__device__ float g_U[2 * 128 * 64];     // U_h = Wfc_h @ Wmerge2_h

__device__ __forceinline__ float sigmoidf_(float v) { return 1.f / (1.f + __expf(-v)); }

__device__ __forceinline__ unsigned f2tf(float v) {
    unsigned r;
    asm("cvt.rna.tf32.f32 %0, %1;" : "=r"(r) : "f"(v));
    return r;
}

__device__ __forceinline__ void mma_tf32(float c[4], unsigned a0, unsigned a1,
                                         unsigned a2, unsigned a3,
                                         unsigned b0, unsigned b1) {
    asm volatile(
        "mma.sync.aligned.m16n8k8.row.col.f32.tf32.tf32.f32 "
        "{%0,%1,%2,%3}, {%4,%5,%6,%7}, {%8,%9}, {%0,%1,%2,%3};"
        : "+f"(c[0]), "+f"(c[1]), "+f"(c[2]), "+f"(c[3])
        : "r"(a0), "r"(a1), "r"(a2), "r"(a3), "r"(b0), "r"(b1));
}

#define AS_STRIDE 140
#define BS_STRIDE 72
#define MS_STRIDE 76
#define K1_SMEM ((64 * AS_STRIDE + 128 * BS_STRIDE) * 4)   // 72704 B
#define K3_SMEM ((64 * AS_STRIDE + 128 * BS_STRIDE + 64 * MS_STRIDE) * 4)  // 92160 B

// ---------------- K0a: fold attn vectors -----------------------------------
__global__ void k0_fold_attn(const float* __restrict__ Wfc,
                             const float* __restrict__ al,
                             const float* __restrict__ ar) {
    int k = threadIdx.x;  // 128
#pragma unroll
    for (int h = 0; h < 2; ++h) {
        float sl = 0.f, sr = 0.f;
#pragma unroll 8
        for (int q = 0; q < 64; ++q) {
            float w = Wfc[k * 128 + h * 64 + q];
            sl += w * al[h * 64 + q];
            sr += w * ar[h * 64 + q];
        }
        g_vlr[k * 4 + h] = sl;
        g_vlr[k * 4 + 2 + h] = sr;
    }
}

// ---------------- K0b: U_h = Wfc_h @ Wmerge2_h -----------------------------
__global__ void k0_fold_U(const float* __restrict__ Wfc,
                          const float* __restrict__ Wmerge) {
    int k = blockIdx.x, h = blockIdx.y, c = threadIdx.x;
    float s = 0.f;
#pragma unroll 8
    for (int q = 0; q < 64; ++q)
        s += Wfc[k * 128 + h * 64 + q] * Wmerge[(128 + h * 64 + q) * 64 + c];
    g_U[(h * 128 + k) * 64 + c] = s;
}

// ---------------- K1: per-node record: y0,y1,z + 8 scalars -----------------
__global__ __launch_bounds__(256) void k1_node_linear(
    const float* __restrict__ x, const float* __restrict__ Wm,
    const float* __restrict__ bm, const float* __restrict__ Wg) {
    extern __shared__ float sm[];
    float(*xs)[AS_STRIDE] = (float(*)[AS_STRIDE])sm;
    float(*Bs)[BS_STRIDE] = (float(*)[BS_STRIDE])(sm + 64 * AS_STRIDE);
    const int tid = threadIdx.x, lane = tid & 31, wid = tid >> 5;
    const int n0 = blockIdx.x * 64;
    const int row0 = (wid >> 1) * 16 + (lane >> 2);
    const int colh = (wid & 1) * 32;
    const int kq = lane & 3;
    const int cn = lane >> 2;
    const int node0 = n0 + row0, node1 = node0 + 8;

    for (int idx = tid; idx < 64 * 128; idx += 256) {
        int nn = idx >> 7, k = idx & 127;
        int node = n0 + nn;
        float v = (node < NNODES) ? x[node * 128 + k] : 0.f;
        xs[nn][k] = __uint_as_float(f2tf(v));
    }

    // passes: 0 -> z (Wm,+bm, cbase 128), 1 -> y0 (U0, cbase 0), 2 -> y1 (U1, cbase 64)
    for (int pass = 0; pass < 3; ++pass) {
        __syncthreads();
        for (int idx = tid; idx < 128 * 64; idx += 256) {
            int k = idx >> 6, c = idx & 63;
            float w = (pass == 0) ? Wm[k * 64 + c]
                                  : g_U[((pass - 1) * 128 + k) * 64 + c];
            Bs[k][c] = __uint_as_float(f2tf(w));
        }
        __syncthreads();

        float C[4][4];
#pragma unroll
        for (int nt = 0; nt < 4; ++nt)
#pragma unroll
            for (int e = 0; e < 4; ++e) C[nt][e] = 0.f;

#pragma unroll
        for (int ks = 0; ks < 16; ++ks) {
            int kb = ks * 8;
            unsigned a0 = __float_as_uint(xs[row0][kb + kq]);
            unsigned a1 = __float_as_uint(xs[row0 + 8][kb + kq]);
            unsigned a2 = __float_as_uint(xs[row0][kb + kq + 4]);
            unsigned a3 = __float_as_uint(xs[row0 + 8][kb + kq + 4]);
#pragma unroll
            for (int nt = 0; nt < 4; ++nt) {
                int col = colh + nt * 8 + cn;
                unsigned b0 = __float_as_uint(Bs[kb + kq][col]);
                unsigned b1 = __float_as_uint(Bs[kb + kq + 4][col]);
                mma_tf32(C[nt], a0, a1, a2, a3, b0, b1);
            }
        }

        int cbase = (pass == 0) ? 128 : (pass - 1) * 64;
#pragma unroll
        for (int nt = 0; nt < 4; ++nt) {
            int c0 = colh + nt * 8 + (lane & 3) * 2;
            float ba = 0.f, bb = 0.f;
            if (pass == 0) { ba = bm[c0]; bb = bm[c0 + 1]; }
            if (node0 < NNODES)
                *(float2*)&g_rec[node0 * RECS + cbase + c0] =
                    make_float2(C[nt][0] + ba, C[nt][1] + bb);
            if (node1 < NNODES)
                *(float2*)&g_rec[node1 * RECS + cbase + c0] =
                    make_float2(C[nt][2] + ba, C[nt][3] + bb);
        }
    }

    // tail: 8 scalars per node: el0,el1,er0,er1,xg2_0,xg2_1,xg1_0,xg1_1
    __syncthreads();
    float* vs = (float*)Bs;  // [128][8]
    for (int idx = tid; idx < 128 * 8; idx += 256) {
        int k = idx >> 3, c = idx & 7;
        float v;
        if (c < 4) v = g_vlr[k * 4 + c];
        else if (c < 6) v = Wg[(128 + k) * 2 + (c - 4)];
        else v = Wg[k * 2 + (c - 6)];
        vs[idx] = v;
    }
    __syncthreads();
#pragma unroll
    for (int w = 0; w < 2; ++w) {
        int it = tid + w * 256;
        int nn = it >> 3, c = it & 7;
        float s = 0.f;
#pragma unroll 16
        for (int k = 0; k < 128; ++k) s += xs[nn][k] * vs[k * 8 + c];
        int node = n0 + nn;
        if (node < NNODES) g_rec[node * RECS + 192 + c] = s;
    }
}

// ---------------- K2: gather + softmax + gate + weighted-y -----------------
__global__ __launch_bounds__(128) void k2_aggregate(
    const int* __restrict__ src, const float* __restrict__ Wg,
    const float* __restrict__ bg) {
    const int n = blockIdx.x;
    const int t = threadIdx.x;  // 128
    __shared__ int ssrc[16];
    __shared__ float sex[16][4];   // el0, el1, xg2_0, xg2_1 per edge
    __shared__ float se[2][16];
    __shared__ float salpha[2][16];
    __shared__ float sred[2][2];   // [warp][head] gate partials
    __shared__ float sgate[2];
    __shared__ float syw1[64];

    if (t < 16) ssrc[t] = src[n * DEGC + t];
    __syncthreads();

    float val[16];
    float mz = -3.4e38f;
#pragma unroll
    for (int j = 0; j < 16; ++j) {
        const float* r = g_rec + (size_t)ssrc[j] * RECS;
        val[j] = r[t];                     // t<64: y0[t]; t>=64: y1[t-64]
        if (t < 72) {
            float v2 = r[128 + t];         // t<64: z[t]; 64..71: extras
            if (t < 64) mz = fmaxf(mz, v2);
            else if (t == 64) sex[j][0] = v2;       // el0
            else if (t == 65) sex[j][1] = v2;       // el1
            else if (t == 68) sex[j][2] = v2;       // xg2_0
            else if (t == 69) sex[j][3] = v2;       // xg2_1
        }
    }
    __syncthreads();

    // e = leaky(el[src] + er[n])
    if (t < 32) {
        int j = t >> 1, h = t & 1;
        float e = sex[j][h] + g_rec[(size_t)n * RECS + 194 + h];
        se[h][j] = (e > 0.f) ? e : 0.2f * e;
    }

    // gate: mz . Wg3 partial reduce (warps 0,1)
    if (t < 64) {
        float p0 = mz * Wg[(256 + t) * 2 + 0];
        float p1 = mz * Wg[(256 + t) * 2 + 1];
#pragma unroll
        for (int o = 16; o > 0; o >>= 1) {
            p0 += __shfl_down_sync(0xffffffffu, p0, o);
            p1 += __shfl_down_sync(0xffffffffu, p1, o);
        }
        if ((t & 31) == 0) { sred[t >> 5][0] = p0; sred[t >> 5][1] = p1; }
    }
    __syncthreads();

    if (t < 2) {
        // softmax over edges for head t
        float m = -3.4e38f;
#pragma unroll
        for (int j = 0; j < 16; ++j) m = fmaxf(m, se[t][j]);
        float ssum = 0.f;
#pragma unroll
        for (int j = 0; j < 16; ++j) {
            float v = __expf(se[t][j] - m);
            salpha[t][j] = v;
            ssum += v;
        }
        float inv = 1.f / fmaxf(ssum, 1e-12f);
#pragma unroll
        for (int j = 0; j < 16; ++j) salpha[t][j] *= inv;

        // gate for head t
        float xg2s = 0.f;
#pragma unroll
        for (int j = 0; j < 16; ++j) xg2s += sex[j][2 + t];
        float arg = g_rec[(size_t)n * RECS + 198 + t]   // xg1
                  + 0.0625f * xg2s
                  + sred[0][t] + sred[1][t]
                  + bg[t];
        sgate[t] = sigmoidf_(arg);
    }
    __syncthreads();

    // alpha-weighted y sums
    const int h = t >> 6;
    float s = 0.f;
#pragma unroll
    for (int j = 0; j < 16; ++j) s += salpha[h][j] * val[j];
    if (t >= 64) syw1[t - 64] = s;
    __syncthreads();
    if (t < 64)
        g_gy[(size_t)n * 64 + t] = sgate[0] * s + sgate[1] * syw1[t];
}

// ---------------- K3 fused: meso = x@W1 + gy + bmerge ; GRU ; out ----------
__global__ __launch_bounds__(256) void k3_fused(
    const float* __restrict__ x, const float* __restrict__ Wmerge,
    const float* __restrict__ bmerge,
    const float* __restrict__ hin, const float* __restrict__ W_ih,
    const float* __restrict__ W_hh, const float* __restrict__ b_ih,
    const float* __restrict__ b_hh, const float* __restrict__ Wout,
    const float* __restrict__ bout, float* __restrict__ out) {
    extern __shared__ float sm[];
    float(*xs)[AS_STRIDE] = (float(*)[AS_STRIDE])sm;
    float(*Bs)[BS_STRIDE] = (float(*)[BS_STRIDE])(sm + 64 * AS_STRIDE);
    float(*ms)[MS_STRIDE] = (float(*)[MS_STRIDE])(sm + 64 * AS_STRIDE + 128 * BS_STRIDE);
    float(*hs)[MS_STRIDE] = (float(*)[MS_STRIDE])sm;                       // alias
    float(*nh)[MS_STRIDE] = (float(*)[MS_STRIDE])(sm + 64 * MS_STRIDE);    // alias
    float(*wt)[BS_STRIDE] = (float(*)[BS_STRIDE])(sm + 2 * 64 * MS_STRIDE);// alias

    const int tid = threadIdx.x, lane = tid & 31, wid = tid >> 5;
    const int n0 = blockIdx.x * 64;
    const int row0 = (wid >> 1) * 16 + (lane >> 2);
    const int colh = (wid & 1) * 32;
    const int kq = lane & 3;
    const int cn = lane >> 2;
    const int node0 = n0 + row0, node1 = node0 + 8;

    // stage A: single K=128 GEMM (x @ Wmerge[0:128])
    for (int idx = tid; idx < 64 * 128; idx += 256) {
        int nn = idx >> 7, k = idx & 127;
        int node = n0 + nn;
        float v = (node < NNODES) ? x[node * 128 + k] : 0.f;
        xs[nn][k] = __uint_as_float(f2tf(v));
    }
    for (int idx = tid; idx < 128 * 64; idx += 256) {
        int k = idx >> 6, c = idx & 63;
        Bs[k][c] = __uint_as_float(f2tf(Wmerge[k * 64 + c]));
    }
    __syncthreads();

    float Cm[4][4];
#pragma unroll
    for (int nt = 0; nt < 4; ++nt)
#pragma unroll
        for (int e = 0; e < 4; ++e) Cm[nt][e] = 0.f;
#pragma unroll
    for (int ks = 0; ks < 16; ++ks) {
        int kb = ks * 8;
        unsigned a0 = __float_as_uint(xs[row0][kb + kq]);
        unsigned a1 = __float_as_uint(xs[row0 + 8][kb + kq]);
        unsigned a2 = __float_as_uint(xs[row0][kb + kq + 4]);
        unsigned a3 = __float_as_uint(xs[row0 + 8][kb + kq + 4]);
#pragma unroll
        for (int nt = 0; nt < 4; ++nt) {
            int col = colh + nt * 8 + cn;
            unsigned b0 = __float_as_uint(Bs[kb + kq][col]);
            unsigned b1 = __float_as_uint(Bs[kb + kq + 4][col]);
            mma_tf32(Cm[nt], a0, a1, a2, a3, b0, b1);
        }
    }
    __syncthreads();  // xs/Bs dead

    // meso = Cm + gy + bmerge -> ms (tf32)
#pragma unroll
    for (int nt = 0; nt < 4; ++nt) {
        int c0 = colh + nt * 8 + (lane & 3) * 2;
        float ba = bmerge[c0], bb = bmerge[c0 + 1];
        float2 gy0 = (node0 < NNODES) ? *(const float2*)&g_gy[(size_t)node0 * 64 + c0]
                                      : make_float2(0.f, 0.f);
        float2 gy1 = (node1 < NNODES) ? *(const float2*)&g_gy[(size_t)node1 * 64 + c0]
                                      : make_float2(0.f, 0.f);
        ms[row0][c0]         = __uint_as_float(f2tf(Cm[nt][0] + gy0.x + ba));
        ms[row0][c0 + 1]     = __uint_as_float(f2tf(Cm[nt][1] + gy0.y + bb));
        ms[row0 + 8][c0]     = __uint_as_float(f2tf(Cm[nt][2] + gy1.x + ba));
        ms[row0 + 8][c0 + 1] = __uint_as_float(f2tf(Cm[nt][3] + gy1.y + bb));
    }

    for (int idx = tid; idx < 64 * 64; idx += 256) {
        int nn = idx >> 6, k = idx & 63;
        int node = n0 + nn;
        hs[nn][k] = (node < NNODES) ? hin[node * 64 + k] : 0.f;
    }

    // stage B: GRU
    float rr[4][4], zz[4][4];
    for (int g = 0; g < 3; ++g) {
        float ai[4][4], ah[4][4];
        __syncthreads();
        for (int idx = tid; idx < 64 * 64; idx += 256) {
            int c = idx >> 6, k = idx & 63;
            wt[k][c] = __uint_as_float(f2tf(W_ih[(g * 64 + c) * 64 + k]));
        }
        __syncthreads();
#pragma unroll
        for (int nt = 0; nt < 4; ++nt)
#pragma unroll
            for (int e = 0; e < 4; ++e) ai[nt][e] = 0.f;
#pragma unroll
        for (int ks = 0; ks < 8; ++ks) {
            int kb = ks * 8;
            unsigned a0 = __float_as_uint(ms[row0][kb + kq]);
            unsigned a1 = __float_as_uint(ms[row0 + 8][kb + kq]);
            unsigned a2 = __float_as_uint(ms[row0][kb + kq + 4]);
            unsigned a3 = __float_as_uint(ms[row0 + 8][kb + kq + 4]);
#pragma unroll
            for (int nt = 0; nt < 4; ++nt) {
                int col = colh + nt * 8 + cn;
                unsigned b0 = __float_as_uint(wt[kb + kq][col]);
                unsigned b1 = __float_as_uint(wt[kb + kq + 4][col]);
                mma_tf32(ai[nt], a0, a1, a2, a3, b0, b1);
            }
        }
        __syncthreads();
        for (int idx = tid; idx < 64 * 64; idx += 256) {
            int c = idx >> 6, k = idx & 63;
            wt[k][c] = __uint_as_float(f2tf(W_hh[(g * 64 + c) * 64 + k]));
        }
        __syncthreads();
#pragma unroll
        for (int nt = 0; nt < 4; ++nt)
#pragma unroll
            for (int e = 0; e < 4; ++e) ah[nt][e] = 0.f;
#pragma unroll
        for (int ks = 0; ks < 8; ++ks) {
            int kb = ks * 8;
            unsigned h0 = __float_as_uint(hs[row0][kb + kq]);
            unsigned h1 = __float_as_uint(hs[row0 + 8][kb + kq]);
            unsigned h2 = __float_as_uint(hs[row0][kb + kq + 4]);
            unsigned h3 = __float_as_uint(hs[row0 + 8][kb + kq + 4]);
#pragma unroll
            for (int nt = 0; nt < 4; ++nt) {
                int col = colh + nt * 8 + cn;
                unsigned b0 = __float_as_uint(wt[kb + kq][col]);
                unsigned b1 = __float_as_uint(wt[kb + kq + 4][col]);
                mma_tf32(ah[nt], h0, h1, h2, h3, b0, b1);
            }
        }

#pragma unroll
        for (int nt = 0; nt < 4; ++nt) {
#pragma unroll
            for (int e = 0; e < 4; ++e) {
                int c = colh + nt * 8 + (lane & 3) * 2 + (e & 1);
                int r = row0 + (e >> 1) * 8;
                float gi = ai[nt][e] + b_ih[g * 64 + c];
                float gh = ah[nt][e] + b_hh[g * 64 + c];
                if (g == 0) {
                    rr[nt][e] = sigmoidf_(gi + gh);
                } else if (g == 1) {
                    zz[nt][e] = sigmoidf_(gi + gh);
                } else {
                    float ng = tanhf(gi + rr[nt][e] * gh);
                    float hv = hs[r][c];
                    float v = (1.f - zz[nt][e]) * ng + zz[nt][e] * hv;
                    int node = n0 + r;
                    if (node < NNODES)
                        out[(size_t)NNODES * 64 + (size_t)node * 64 + c] = v;
                    nh[r][c] = __uint_as_float(f2tf(v));
                }
            }
        }
    }

    // output projection
    __syncthreads();
    for (int idx = tid; idx < 64 * 64; idx += 256) {
        int k = idx >> 6, c = idx & 63;
        wt[k][c] = __uint_as_float(f2tf(Wout[k * 64 + c]));
    }
    __syncthreads();

    float C[4][4];
#pragma unroll
    for (int nt = 0; nt < 4; ++nt)
#pragma unroll
        for (int e = 0; e < 4; ++e) C[nt][e] = 0.f;
#pragma unroll
    for (int ks = 0; ks < 8; ++ks) {
        int kb = ks * 8;
        unsigned a0 = __float_as_uint(nh[row0][kb + kq]);
        unsigned a1 = __float_as_uint(nh[row0 + 8][kb + kq]);
        unsigned a2 = __float_as_uint(nh[row0][kb + kq + 4]);
        unsigned a3 = __float_as_uint(nh[row0 + 8][kb + kq + 4]);
#pragma unroll
        for (int nt = 0; nt < 4; ++nt) {
            int col = colh + nt * 8 + cn;
            unsigned b0 = __float_as_uint(wt[kb + kq][col]);
            unsigned b1 = __float_as_uint(wt[kb + kq + 4][col]);
            mma_tf32(C[nt], a0, a1, a2, a3, b0, b1);
        }
    }
#pragma unroll
    for (int nt = 0; nt < 4; ++nt) {
        int c0 = colh + nt * 8 + (lane & 3) * 2;
        float ba = bout[c0], bb = bout[c0 + 1];
        if (node0 < NNODES)
            *(float2*)&out[(size_t)node0 * 64 + c0] = make_float2(C[nt][0] + ba, C[nt][1] + bb);
        if (node1 < NNODES)
            *(float2*)&out[(size_t)node1 * 64 + c0] = make_float2(C[nt][2] + ba, C[nt][3] + bb);
    }
}

// ---------------- launch ---------------------------------------------------
extern "C" void kernel_launch(void* const* d_in, const int* in_sizes, int n_in,
                              void* d_out, int out_size) {
    const float* x    = (const float*)d_in[0];
    const float* hin  = (const float*)d_in[1];
    const int*   srcp = (const int*)d_in[2];
    const float* Wm   = (const float*)d_in[4];
    const float* bm   = (const float*)d_in[5];
    const float* Wg   = (const float*)d_in[6];
    const float* bg   = (const float*)d_in[7];
    const float* Wfc  = (const float*)d_in[8];
    const float* al   = (const float*)d_in[9];
    const float* ar   = (const float*)d_in[10];
    const float* Wmg  = (const float*)d_in[11];
    const float* bmg  = (const float*)d_in[12];
    const float* Wih  = (const float*)d_in[13];
    const float* Whh  = (const float*)d_in[14];
    const float* bih  = (const float*)d_in[15];
    const float* bhh  = (const float*)d_in[16];
    const float* Wo   = (const float*)d_in[17];
    const float* bo   = (const float*)d_in[18];
    float* out = (float*)d_out;

    cudaFuncSetAttribute(k1_node_linear, cudaFuncAttributeMaxDynamicSharedMemorySize, K1_SMEM);
    cudaFuncSetAttribute(k3_fused, cudaFuncAttributeMaxDynamicSharedMemorySize, K3_SMEM);

    int nb = (NNODES + 63) / 64;
    k0_fold_attn<<<1, 128>>>(Wfc, al, ar);
    k0_fold_U<<<dim3(128, 2), 64>>>(Wfc, Wmg);
    k1_node_linear<<<nb, 256, K1_SMEM>>>(x, Wm, bm, Wg);
    k2_aggregate<<<NNODES, 128>>>(srcp, Wg, bg);
    k3_fused<<<nb, 256, K3_SMEM>>>(x, Wmg, bmg, hin, Wih, Whh, bih, bhh, Wo, bo, out);
}

// round 7
// speedup vs baseline: 2.0584x; 2.0584x over previous
#include <cuda_runtime.h>
#include <math.h>

#define NNODES 50000
#define DEGC 16
#define RECS 208   // record stride (floats): y[128] z[64] el[2] er[2] xg2[2] xg1[2]

// ---------------- scratch (device globals) ---------------------------------
__device__ float g_rec[NNODES * RECS];
__device__ float g_gy[NNODES * 64];     // gate-weighted attn contribution (merge space)
__device__ float g_vlr[128 * 4];        // [k][el0,el1,er0,er1]
__device__ float g_U[2 * 128 * 64];     // U_h = Wfc_h @ Wmerge2_h

__device__ __forceinline__ float sigmoidf_(float v) { return 1.f / (1.f + __expf(-v)); }

__device__ __forceinline__ unsigned f2tf(float v) {
    unsigned r;
    asm("cvt.rna.tf32.f32 %0, %1;" : "=r"(r) : "f"(v));
    return r;
}

__device__ __forceinline__ void mma_tf32(float c[4], unsigned a0, unsigned a1,
                                         unsigned a2, unsigned a3,
                                         unsigned b0, unsigned b1) {
    asm volatile(
        "mma.sync.aligned.m16n8k8.row.col.f32.tf32.tf32.f32 "
        "{%0,%1,%2,%3}, {%4,%5,%6,%7}, {%8,%9}, {%0,%1,%2,%3};"
        : "+f"(c[0]), "+f"(c[1]), "+f"(c[2]), "+f"(c[3])
        : "r"(a0), "r"(a1), "r"(a2), "r"(a3), "r"(b0), "r"(b1));
}

#define AS_STRIDE 140
#define BS_STRIDE 72
#define MS_STRIDE 76
#define K1_SMEM ((64 * AS_STRIDE + 128 * BS_STRIDE) * 4)   // 72704 B
#define K3_SMEM ((64 * AS_STRIDE + 128 * BS_STRIDE + 64 * MS_STRIDE) * 4)  // 92160 B

// ---------------- K0a: fold attn vectors -----------------------------------
__global__ void k0_fold_attn(const float* __restrict__ Wfc,
                             const float* __restrict__ al,
                             const float* __restrict__ ar) {
    int k = threadIdx.x;  // 128
#pragma unroll
    for (int h = 0; h < 2; ++h) {
        float sl = 0.f, sr = 0.f;
#pragma unroll 8
        for (int q = 0; q < 64; ++q) {
            float w = Wfc[k * 128 + h * 64 + q];
            sl += w * al[h * 64 + q];
            sr += w * ar[h * 64 + q];
        }
        g_vlr[k * 4 + h] = sl;
        g_vlr[k * 4 + 2 + h] = sr;
    }
}

// ---------------- K0b: U_h = Wfc_h @ Wmerge2_h -----------------------------
__global__ void k0_fold_U(const float* __restrict__ Wfc,
                          const float* __restrict__ Wmerge) {
    int k = blockIdx.x, h = blockIdx.y, c = threadIdx.x;
    float s = 0.f;
#pragma unroll 8
    for (int q = 0; q < 64; ++q)
        s += Wfc[k * 128 + h * 64 + q] * Wmerge[(128 + h * 64 + q) * 64 + c];
    g_U[(h * 128 + k) * 64 + c] = s;
}

// ---------------- K1: per-node record: y0,y1,z + 8 scalars -----------------
__global__ __launch_bounds__(256) void k1_node_linear(
    const float* __restrict__ x, const float* __restrict__ Wm,
    const float* __restrict__ bm, const float* __restrict__ Wg) {
    extern __shared__ float sm[];
    float(*xs)[AS_STRIDE] = (float(*)[AS_STRIDE])sm;
    float(*Bs)[BS_STRIDE] = (float(*)[BS_STRIDE])(sm + 64 * AS_STRIDE);
    const int tid = threadIdx.x, lane = tid & 31, wid = tid >> 5;
    const int n0 = blockIdx.x * 64;
    const int row0 = (wid >> 1) * 16 + (lane >> 2);
    const int colh = (wid & 1) * 32;
    const int kq = lane & 3;
    const int cn = lane >> 2;
    const int node0 = n0 + row0, node1 = node0 + 8;

    for (int idx = tid; idx < 64 * 128; idx += 256) {
        int nn = idx >> 7, k = idx & 127;
        int node = n0 + nn;
        float v = (node < NNODES) ? x[node * 128 + k] : 0.f;
        xs[nn][k] = __uint_as_float(f2tf(v));
    }

    // passes: 0 -> z (Wm,+bm, cbase 128), 1 -> y0 (U0, cbase 0), 2 -> y1 (U1, cbase 64)
    for (int pass = 0; pass < 3; ++pass) {
        __syncthreads();
        for (int idx = tid; idx < 128 * 64; idx += 256) {
            int k = idx >> 6, c = idx & 63;
            float w = (pass == 0) ? Wm[k * 64 + c]
                                  : g_U[((pass - 1) * 128 + k) * 64 + c];
            Bs[k][c] = __uint_as_float(f2tf(w));
        }
        __syncthreads();

        float C[4][4];
#pragma unroll
        for (int nt = 0; nt < 4; ++nt)
#pragma unroll
            for (int e = 0; e < 4; ++e) C[nt][e] = 0.f;

#pragma unroll
        for (int ks = 0; ks < 16; ++ks) {
            int kb = ks * 8;
            unsigned a0 = __float_as_uint(xs[row0][kb + kq]);
            unsigned a1 = __float_as_uint(xs[row0 + 8][kb + kq]);
            unsigned a2 = __float_as_uint(xs[row0][kb + kq + 4]);
            unsigned a3 = __float_as_uint(xs[row0 + 8][kb + kq + 4]);
#pragma unroll
            for (int nt = 0; nt < 4; ++nt) {
                int col = colh + nt * 8 + cn;
                unsigned b0 = __float_as_uint(Bs[kb + kq][col]);
                unsigned b1 = __float_as_uint(Bs[kb + kq + 4][col]);
                mma_tf32(C[nt], a0, a1, a2, a3, b0, b1);
            }
        }

        int cbase = (pass == 0) ? 128 : (pass - 1) * 64;
#pragma unroll
        for (int nt = 0; nt < 4; ++nt) {
            int c0 = colh + nt * 8 + (lane & 3) * 2;
            float ba = 0.f, bb = 0.f;
            if (pass == 0) { ba = bm[c0]; bb = bm[c0 + 1]; }
            if (node0 < NNODES)
                *(float2*)&g_rec[node0 * RECS + cbase + c0] =
                    make_float2(C[nt][0] + ba, C[nt][1] + bb);
            if (node1 < NNODES)
                *(float2*)&g_rec[node1 * RECS + cbase + c0] =
                    make_float2(C[nt][2] + ba, C[nt][3] + bb);
        }
    }

    // tail: 8 scalars per node: el0,el1,er0,er1,xg2_0,xg2_1,xg1_0,xg1_1
    __syncthreads();
    float* vs = (float*)Bs;  // [128][8]
    for (int idx = tid; idx < 128 * 8; idx += 256) {
        int k = idx >> 3, c = idx & 7;
        float v;
        if (c < 4) v = g_vlr[k * 4 + c];
        else if (c < 6) v = Wg[(128 + k) * 2 + (c - 4)];
        else v = Wg[k * 2 + (c - 6)];
        vs[idx] = v;
    }
    __syncthreads();
#pragma unroll
    for (int w = 0; w < 2; ++w) {
        int it = tid + w * 256;
        int nn = it >> 3, c = it & 7;
        float s = 0.f;
#pragma unroll 16
        for (int k = 0; k < 128; ++k) s += xs[nn][k] * vs[k * 8 + c];
        int node = n0 + nn;
        if (node < NNODES) g_rec[node * RECS + 192 + c] = s;
    }
}

// ---------------- K2: one warp per node, zero barriers ---------------------
__global__ __launch_bounds__(256) void k2_aggregate(
    const int* __restrict__ src, const float* __restrict__ Wg,
    const float* __restrict__ bg) {
    const unsigned FULL = 0xffffffffu;
    const int n = blockIdx.x * 8 + ((threadIdx.x) >> 5);
    if (n >= NNODES) return;
    const int lane = threadIdx.x & 31;
    const int j16 = lane & 15, h = lane >> 4;

    // each lane: src of edge (lane&15)
    int srcj = src[n * DEGC + j16];

    // ---- e + softmax per head (16-lane butterfly groups) ----
    float el = g_rec[(size_t)srcj * RECS + 192 + h];
    float er = g_rec[(size_t)n * RECS + 194 + h];
    float e = el + er;
    e = (e > 0.f) ? e : 0.2f * e;
    float m = e;
#pragma unroll
    for (int o = 8; o > 0; o >>= 1) m = fmaxf(m, __shfl_xor_sync(FULL, m, o));
    float ee = __expf(e - m);
    float s = ee;
#pragma unroll
    for (int o = 8; o > 0; o >>= 1) s += __shfl_xor_sync(FULL, s, o);
    float alpha = ee / fmaxf(s, 1e-12f);

    // ---- xg2 mean term (sum over edges per head) ----
    float xg2 = g_rec[(size_t)srcj * RECS + 196 + h];
#pragma unroll
    for (int o = 8; o > 0; o >>= 1) xg2 += __shfl_xor_sync(FULL, xg2, o);

    // ---- z max: lane owns z cols 2*lane, 2*lane+1 (16 independent float2) -
    float mz0 = -3.4e38f, mz1 = -3.4e38f;
#pragma unroll
    for (int j = 0; j < 16; ++j) {
        int sj = __shfl_sync(FULL, srcj, j);
        float2 z2 = *(const float2*)&g_rec[(size_t)sj * RECS + 128 + 2 * lane];
        mz0 = fmaxf(mz0, z2.x);
        mz1 = fmaxf(mz1, z2.y);
    }
    // gate max_z dot for both heads, warp-reduce
    float p0 = mz0 * Wg[(256 + 2 * lane) * 2 + 0] + mz1 * Wg[(256 + 2 * lane + 1) * 2 + 0];
    float p1 = mz0 * Wg[(256 + 2 * lane) * 2 + 1] + mz1 * Wg[(256 + 2 * lane + 1) * 2 + 1];
#pragma unroll
    for (int o = 16; o > 0; o >>= 1) {
        p0 += __shfl_xor_sync(FULL, p0, o);
        p1 += __shfl_xor_sync(FULL, p1, o);
    }
    float g3 = (h == 0) ? p0 : p1;
    float xg1 = g_rec[(size_t)n * RECS + 198 + h];
    float gate = sigmoidf_(xg1 + 0.0625f * xg2 + g3 + bg[h]);

    // ---- alpha-weighted y: lane owns cols 4L..4L+3 (head = L>>4) ----------
    float4 acc = make_float4(0.f, 0.f, 0.f, 0.f);
#pragma unroll
    for (int j = 0; j < 16; ++j) {
        int sj = __shfl_sync(FULL, srcj, j);
        float a = __shfl_sync(FULL, alpha, (lane & 16) | j);
        float4 y4 = *(const float4*)&g_rec[(size_t)sj * RECS + 4 * lane];
        acc.x += a * y4.x; acc.y += a * y4.y; acc.z += a * y4.z; acc.w += a * y4.w;
    }

    // combine heads: lane L (<16) holds yw0 cols, lane L+16 holds yw1 cols
    float got = __shfl_xor_sync(FULL, gate, 16);
    float ox = __shfl_xor_sync(FULL, acc.x, 16);
    float oy = __shfl_xor_sync(FULL, acc.y, 16);
    float oz = __shfl_xor_sync(FULL, acc.z, 16);
    float ow = __shfl_xor_sync(FULL, acc.w, 16);
    if (lane < 16) {
        float4 gy;
        gy.x = gate * acc.x + got * ox;
        gy.y = gate * acc.y + got * oy;
        gy.z = gate * acc.z + got * oz;
        gy.w = gate * acc.w + got * ow;
        *(float4*)&g_gy[(size_t)n * 64 + 4 * lane] = gy;
    }
}

// ---------------- K3 fused: meso = x@W1 + gy + bmerge ; GRU ; out ----------
__global__ __launch_bounds__(256) void k3_fused(
    const float* __restrict__ x, const float* __restrict__ Wmerge,
    const float* __restrict__ bmerge,
    const float* __restrict__ hin, const float* __restrict__ W_ih,
    const float* __restrict__ W_hh, const float* __restrict__ b_ih,
    const float* __restrict__ b_hh, const float* __restrict__ Wout,
    const float* __restrict__ bout, float* __restrict__ out) {
    extern __shared__ float sm[];
    float(*xs)[AS_STRIDE] = (float(*)[AS_STRIDE])sm;
    float(*Bs)[BS_STRIDE] = (float(*)[BS_STRIDE])(sm + 64 * AS_STRIDE);
    float(*ms)[MS_STRIDE] = (float(*)[MS_STRIDE])(sm + 64 * AS_STRIDE + 128 * BS_STRIDE);
    float(*hs)[MS_STRIDE] = (float(*)[MS_STRIDE])sm;                       // alias
    float(*nh)[MS_STRIDE] = (float(*)[MS_STRIDE])(sm + 64 * MS_STRIDE);    // alias
    float(*wt)[BS_STRIDE] = (float(*)[BS_STRIDE])(sm + 2 * 64 * MS_STRIDE);// alias

    const int tid = threadIdx.x, lane = tid & 31, wid = tid >> 5;
    const int n0 = blockIdx.x * 64;
    const int row0 = (wid >> 1) * 16 + (lane >> 2);
    const int colh = (wid & 1) * 32;
    const int kq = lane & 3;
    const int cn = lane >> 2;
    const int node0 = n0 + row0, node1 = node0 + 8;

    // stage A: single K=128 GEMM (x @ Wmerge[0:128])
    for (int idx = tid; idx < 64 * 128; idx += 256) {
        int nn = idx >> 7, k = idx & 127;
        int node = n0 + nn;
        float v = (node < NNODES) ? x[node * 128 + k] : 0.f;
        xs[nn][k] = __uint_as_float(f2tf(v));
    }
    for (int idx = tid; idx < 128 * 64; idx += 256) {
        int k = idx >> 6, c = idx & 63;
        Bs[k][c] = __uint_as_float(f2tf(Wmerge[k * 64 + c]));
    }
    __syncthreads();

    float Cm[4][4];
#pragma unroll
    for (int nt = 0; nt < 4; ++nt)
#pragma unroll
        for (int e = 0; e < 4; ++e) Cm[nt][e] = 0.f;
#pragma unroll
    for (int ks = 0; ks < 16; ++ks) {
        int kb = ks * 8;
        unsigned a0 = __float_as_uint(xs[row0][kb + kq]);
        unsigned a1 = __float_as_uint(xs[row0 + 8][kb + kq]);
        unsigned a2 = __float_as_uint(xs[row0][kb + kq + 4]);
        unsigned a3 = __float_as_uint(xs[row0 + 8][kb + kq + 4]);
#pragma unroll
        for (int nt = 0; nt < 4; ++nt) {
            int col = colh + nt * 8 + cn;
            unsigned b0 = __float_as_uint(Bs[kb + kq][col]);
            unsigned b1 = __float_as_uint(Bs[kb + kq + 4][col]);
            mma_tf32(Cm[nt], a0, a1, a2, a3, b0, b1);
        }
    }
    __syncthreads();  // xs/Bs dead

    // meso = Cm + gy + bmerge -> ms (tf32)
#pragma unroll
    for (int nt = 0; nt < 4; ++nt) {
        int c0 = colh + nt * 8 + (lane & 3) * 2;
        float ba = bmerge[c0], bb = bmerge[c0 + 1];
        float2 gy0 = (node0 < NNODES) ? *(const float2*)&g_gy[(size_t)node0 * 64 + c0]
                                      : make_float2(0.f, 0.f);
        float2 gy1 = (node1 < NNODES) ? *(const float2*)&g_gy[(size_t)node1 * 64 + c0]
                                      : make_float2(0.f, 0.f);
        ms[row0][c0]         = __uint_as_float(f2tf(Cm[nt][0] + gy0.x + ba));
        ms[row0][c0 + 1]     = __uint_as_float(f2tf(Cm[nt][1] + gy0.y + bb));
        ms[row0 + 8][c0]     = __uint_as_float(f2tf(Cm[nt][2] + gy1.x + ba));
        ms[row0 + 8][c0 + 1] = __uint_as_float(f2tf(Cm[nt][3] + gy1.y + bb));
    }

    for (int idx = tid; idx < 64 * 64; idx += 256) {
        int nn = idx >> 6, k = idx & 63;
        int node = n0 + nn;
        hs[nn][k] = (node < NNODES) ? hin[node * 64 + k] : 0.f;
    }

    // stage B: GRU
    float rr[4][4], zz[4][4];
    for (int g = 0; g < 3; ++g) {
        float ai[4][4], ah[4][4];
        __syncthreads();
        for (int idx = tid; idx < 64 * 64; idx += 256) {
            int c = idx >> 6, k = idx & 63;
            wt[k][c] = __uint_as_float(f2tf(W_ih[(g * 64 + c) * 64 + k]));
        }
        __syncthreads();
#pragma unroll
        for (int nt = 0; nt < 4; ++nt)
#pragma unroll
            for (int e = 0; e < 4; ++e) ai[nt][e] = 0.f;
#pragma unroll
        for (int ks = 0; ks < 8; ++ks) {
            int kb = ks * 8;
            unsigned a0 = __float_as_uint(ms[row0][kb + kq]);
            unsigned a1 = __float_as_uint(ms[row0 + 8][kb + kq]);
            unsigned a2 = __float_as_uint(ms[row0][kb + kq + 4]);
            unsigned a3 = __float_as_uint(ms[row0 + 8][kb + kq + 4]);
#pragma unroll
            for (int nt = 0; nt < 4; ++nt) {
                int col = colh + nt * 8 + cn;
                unsigned b0 = __float_as_uint(wt[kb + kq][col]);
                unsigned b1 = __float_as_uint(wt[kb + kq + 4][col]);
                mma_tf32(ai[nt], a0, a1, a2, a3, b0, b1);
            }
        }
        __syncthreads();
        for (int idx = tid; idx < 64 * 64; idx += 256) {
            int c = idx >> 6, k = idx & 63;
            wt[k][c] = __uint_as_float(f2tf(W_hh[(g * 64 + c) * 64 + k]));
        }
        __syncthreads();
#pragma unroll
        for (int nt = 0; nt < 4; ++nt)
#pragma unroll
            for (int e = 0; e < 4; ++e) ah[nt][e] = 0.f;
#pragma unroll
        for (int ks = 0; ks < 8; ++ks) {
            int kb = ks * 8;
            unsigned h0 = __float_as_uint(hs[row0][kb + kq]);
            unsigned h1 = __float_as_uint(hs[row0 + 8][kb + kq]);
            unsigned h2 = __float_as_uint(hs[row0][kb + kq + 4]);
            unsigned h3 = __float_as_uint(hs[row0 + 8][kb + kq + 4]);
#pragma unroll
            for (int nt = 0; nt < 4; ++nt) {
                int col = colh + nt * 8 + cn;
                unsigned b0 = __float_as_uint(wt[kb + kq][col]);
                unsigned b1 = __float_as_uint(wt[kb + kq + 4][col]);
                mma_tf32(ah[nt], h0, h1, h2, h3, b0, b1);
            }
        }

#pragma unroll
        for (int nt = 0; nt < 4; ++nt) {
#pragma unroll
            for (int e = 0; e < 4; ++e) {
                int c = colh + nt * 8 + (lane & 3) * 2 + (e & 1);
                int r = row0 + (e >> 1) * 8;
                float gi = ai[nt][e] + b_ih[g * 64 + c];
                float gh = ah[nt][e] + b_hh[g * 64 + c];
                if (g == 0) {
                    rr[nt][e] = sigmoidf_(gi + gh);
                } else if (g == 1) {
                    zz[nt][e] = sigmoidf_(gi + gh);
                } else {
                    float ng = tanhf(gi + rr[nt][e] * gh);
                    float hv = hs[r][c];
                    float v = (1.f - zz[nt][e]) * ng + zz[nt][e] * hv;
                    int node = n0 + r;
                    if (node < NNODES)
                        out[(size_t)NNODES * 64 + (size_t)node * 64 + c] = v;
                    nh[r][c] = __uint_as_float(f2tf(v));
                }
            }
        }
    }

    // output projection
    __syncthreads();
    for (int idx = tid; idx < 64 * 64; idx += 256) {
        int k = idx >> 6, c = idx & 63;
        wt[k][c] = __uint_as_float(f2tf(Wout[k * 64 + c]));
    }
    __syncthreads();

    float C[4][4];
#pragma unroll
    for (int nt = 0; nt < 4; ++nt)
#pragma unroll
        for (int e = 0; e < 4; ++e) C[nt][e] = 0.f;
#pragma unroll
    for (int ks = 0; ks < 8; ++ks) {
        int kb = ks * 8;
        unsigned a0 = __float_as_uint(nh[row0][kb + kq]);
        unsigned a1 = __float_as_uint(nh[row0 + 8][kb + kq]);
        unsigned a2 = __float_as_uint(nh[row0][kb + kq + 4]);
        unsigned a3 = __float_as_uint(nh[row0 + 8][kb + kq + 4]);
#pragma unroll
        for (int nt = 0; nt < 4; ++nt) {
            int col = colh + nt * 8 + cn;
            unsigned b0 = __float_as_uint(wt[kb + kq][col]);
            unsigned b1 = __float_as_uint(wt[kb + kq + 4][col]);
            mma_tf32(C[nt], a0, a1, a2, a3, b0, b1);
        }
    }
#pragma unroll
    for (int nt = 0; nt < 4; ++nt) {
        int c0 = colh + nt * 8 + (lane & 3) * 2;
        float ba = bout[c0], bb = bout[c0 + 1];
        if (node0 < NNODES)
            *(float2*)&out[(size_t)node0 * 64 + c0] = make_float2(C[nt][0] + ba, C[nt][1] + bb);
        if (node1 < NNODES)
            *(float2*)&out[(size_t)node1 * 64 + c0] = make_float2(C[nt][2] + ba, C[nt][3] + bb);
    }
}

// ---------------- launch ---------------------------------------------------
extern "C" void kernel_launch(void* const* d_in, const int* in_sizes, int n_in,
                              void* d_out, int out_size) {
    const float* x    = (const float*)d_in[0];
    const float* hin  = (const float*)d_in[1];
    const int*   srcp = (const int*)d_in[2];
    const float* Wm   = (const float*)d_in[4];
    const float* bm   = (const float*)d_in[5];
    const float* Wg   = (const float*)d_in[6];
    const float* bg   = (const float*)d_in[7];
    const float* Wfc  = (const float*)d_in[8];
    const float* al   = (const float*)d_in[9];
    const float* ar   = (const float*)d_in[10];
    const float* Wmg  = (const float*)d_in[11];
    const float* bmg  = (const float*)d_in[12];
    const float* Wih  = (const float*)d_in[13];
    const float* Whh  = (const float*)d_in[14];
    const float* bih  = (const float*)d_in[15];
    const float* bhh  = (const float*)d_in[16];
    const float* Wo   = (const float*)d_in[17];
    const float* bo   = (const float*)d_in[18];
    float* out = (float*)d_out;

    cudaFuncSetAttribute(k1_node_linear, cudaFuncAttributeMaxDynamicSharedMemorySize, K1_SMEM);
    cudaFuncSetAttribute(k3_fused, cudaFuncAttributeMaxDynamicSharedMemorySize, K3_SMEM);

    int nb = (NNODES + 63) / 64;
    k0_fold_attn<<<1, 128>>>(Wfc, al, ar);
    k0_fold_U<<<dim3(128, 2), 64>>>(Wfc, Wmg);
    k1_node_linear<<<nb, 256, K1_SMEM>>>(x, Wm, bm, Wg);
    k2_aggregate<<<(NNODES + 7) / 8, 256>>>(srcp, Wg, bg);
    k3_fused<<<nb, 256, K3_SMEM>>>(x, Wmg, bmg, hin, Wih, Whh, bih, bhh, Wo, bo, out);
}